// round 2
// baseline (speedup 1.0000x reference)
#include <cuda_runtime.h>
#include <cuda_bf16.h>

// Problem constants (match reference_code)
#define N_NODES 50000
#define DIM     128
#define E_TOTAL 600000

// Scratch: per-node projections. A holds x@W1a^T + b1, B holds x@W1b^T.
__device__ float g_A[N_NODES * DIM];
__device__ float g_B[N_NODES * DIM];
__device__ double g_loss_sum;

__global__ void zero_sum_kernel() {
    g_loss_sum = 0.0;
}

// ---------------------------------------------------------------------------
// Kernel 1: node projection GEMM.
//   half = blockIdx.y: 0 -> A (weights W1[:, 0:128], add b1), 1 -> B (W1[:,128:256])
//   Block tile: 64 rows x 128 cols, K chunked by 32. 256 threads, 4x8 per thread.
// ---------------------------------------------------------------------------
__global__ __launch_bounds__(256) void node_proj_kernel(
    const float* __restrict__ x,    // [N_NODES, 128]
    const float* __restrict__ W1,   // [128, 256] row-major
    const float* __restrict__ b1)   // [128]
{
    const int half = blockIdx.y;
    const int row0 = blockIdx.x * 64;
    const int tid  = threadIdx.x;
    const int tx   = tid & 15;   // col group: cols 8*tx .. 8*tx+7
    const int ty   = tid >> 4;   // row group: rows 4*ty .. 4*ty+3
    const int woff = half * 128; // k-offset into W1 rows

    float* __restrict__ out = half ? g_B : g_A;

    // Padded shared tiles (conflict-aware pitches)
    __shared__ float xs[64 * 33];    // [64 rows][32 k], pitch 33
    __shared__ float ws[32 * 132];   // [32 k][128 j], pitch 132 (16B-aligned rows)

    float acc[4][8];
#pragma unroll
    for (int i = 0; i < 4; i++)
#pragma unroll
        for (int j = 0; j < 8; j++) acc[i][j] = 0.0f;

    for (int kc = 0; kc < 128; kc += 32) {
        // Load x chunk [64 x 32] (coalesced over k)
#pragma unroll
        for (int idx = tid; idx < 64 * 32; idx += 256) {
            int r  = idx >> 5;
            int kk = idx & 31;
            int row = row0 + r;
            xs[r * 33 + kk] = (row < N_NODES) ? x[row * 128 + kc + kk] : 0.0f;
        }
        // Load W chunk [32 k x 128 j] transposed into ws[kk][j] (coalesced over kk)
#pragma unroll
        for (int idx = tid; idx < 32 * 128; idx += 256) {
            int kk = idx & 31;
            int j  = idx >> 5;
            ws[kk * 132 + j] = W1[j * 256 + woff + kc + kk];
        }
        __syncthreads();

#pragma unroll 8
        for (int kk = 0; kk < 32; kk++) {
            float xv[4];
#pragma unroll
            for (int i = 0; i < 4; i++)
                xv[i] = xs[(4 * ty + i) * 33 + kk];
            const float4* wr = (const float4*)(ws + kk * 132 + 8 * tx);
            float4 w0 = wr[0];
            float4 w1 = wr[1];
            float wv[8] = {w0.x, w0.y, w0.z, w0.w, w1.x, w1.y, w1.z, w1.w};
#pragma unroll
            for (int i = 0; i < 4; i++)
#pragma unroll
                for (int j = 0; j < 8; j++)
                    acc[i][j] = fmaf(xv[i], wv[j], acc[i][j]);
        }
        __syncthreads();
    }

    // Fold b1 into A half
    if (half == 0) {
        float bb[8];
#pragma unroll
        for (int j = 0; j < 8; j++) bb[j] = b1[8 * tx + j];
#pragma unroll
        for (int i = 0; i < 4; i++)
#pragma unroll
            for (int j = 0; j < 8; j++) acc[i][j] += bb[j];
    }

    // Store (2x float4 per row per thread, coalesced)
#pragma unroll
    for (int i = 0; i < 4; i++) {
        int row = row0 + 4 * ty + i;
        if (row < N_NODES) {
            float4* o = (float4*)(out + row * 128 + 8 * tx);
            o[0] = make_float4(acc[i][0], acc[i][1], acc[i][2], acc[i][3]);
            o[1] = make_float4(acc[i][4], acc[i][5], acc[i][6], acc[i][7]);
        }
    }
}

// ---------------------------------------------------------------------------
// Kernel 2: edge phase. One warp per edge (grid-stride).
//   z = sum_j relu(A[u][j] + B[v][j]) * w2[j] + b2
//   loss_e = max(z,0) - z*y + log1p(exp(-|z|))   (stable BCE-with-logits)
// NOTE: pairs is int32 — JAX default config silently downcasts the reference's
// requested int64 to int32 (jax_enable_x64 is off in the harness).
// ---------------------------------------------------------------------------
__global__ __launch_bounds__(256) void edge_kernel(
    const int*   __restrict__ pairs,   // [2, E] int32
    const float* __restrict__ labels,  // [E]
    const float* __restrict__ W2,      // [128]
    const float* __restrict__ b2)      // [1]
{
    const int lane = threadIdx.x & 31;
    const int warp_global = (blockIdx.x * blockDim.x + threadIdx.x) >> 5;
    const int nwarps = (gridDim.x * blockDim.x) >> 5;

    const float4 w2 = ((const float4*)W2)[lane];
    const float bias2 = b2[0];

    float acc = 0.0f;

    for (int e = warp_global; e < E_TOTAL; e += nwarps) {
        int u = pairs[e];
        int v = pairs[E_TOTAL + e];
        const float4 a = ((const float4*)(g_A + (size_t)u * DIM))[lane];
        const float4 b = ((const float4*)(g_B + (size_t)v * DIM))[lane];

        float z;
        z = fmaxf(a.x + b.x, 0.0f) * w2.x;
        z = fmaf(fmaxf(a.y + b.y, 0.0f), w2.y, z);
        z = fmaf(fmaxf(a.z + b.z, 0.0f), w2.z, z);
        z = fmaf(fmaxf(a.w + b.w, 0.0f), w2.w, z);

#pragma unroll
        for (int off = 16; off; off >>= 1)
            z += __shfl_xor_sync(0xFFFFFFFFu, z, off);
        z += bias2;

        float y = labels[e];
        float loss = fmaxf(z, 0.0f) - z * y + log1pf(expf(-fabsf(z)));
        acc += loss;
    }

    // acc is identical on all lanes (butterfly gave full sum to every lane);
    // take lane 0 of each warp, reduce across block, one atomic per block.
    __shared__ float wsum[8];
    if (lane == 0) wsum[threadIdx.x >> 5] = acc;
    __syncthreads();
    if (threadIdx.x == 0) {
        float s = 0.0f;
#pragma unroll
        for (int i = 0; i < 8; i++) s += wsum[i];
        atomicAdd(&g_loss_sum, (double)s);
    }
}

__global__ void finalize_kernel(float* __restrict__ out) {
    out[0] = (float)(g_loss_sum / (double)E_TOTAL);
}

// ---------------------------------------------------------------------------
// kernel_launch
// Input order (metadata): x, W1, b1, W2, b2, labels, pairs
// ---------------------------------------------------------------------------
extern "C" void kernel_launch(void* const* d_in, const int* in_sizes, int n_in,
                              void* d_out, int out_size) {
    const float* x      = (const float*)d_in[0];
    const float* W1     = (const float*)d_in[1];
    const float* b1     = (const float*)d_in[2];
    const float* W2     = (const float*)d_in[3];
    const float* b2     = (const float*)d_in[4];
    const float* labels = (const float*)d_in[5];
    const int*   pairs  = (const int*)d_in[6];
    float* out = (float*)d_out;

    zero_sum_kernel<<<1, 1>>>();

    dim3 ggrid((N_NODES + 63) / 64, 2);
    node_proj_kernel<<<ggrid, 256>>>(x, W1, b1);

    edge_kernel<<<1184, 256>>>(pairs, labels, W2, b2);

    finalize_kernel<<<1, 1>>>(out);
}

// round 3
// speedup vs baseline: 1.0166x; 1.0166x over previous
#include <cuda_runtime.h>
#include <cuda_bf16.h>

// Problem constants (match reference_code)
#define N_NODES 50000
#define DIM     128
#define E_TOTAL 600000

// Scratch: per-node projections. A holds x@W1a^T + b1, B holds x@W1b^T.
__device__ float g_A[N_NODES * DIM];
__device__ float g_B[N_NODES * DIM];
__device__ double g_loss_sum;

typedef unsigned long long u64;

// Packed f32x2 helpers (Blackwell sm_103a packed fp32 datapath).
__device__ __forceinline__ u64 pack2_dup(float v) {
    u64 r; asm("mov.b64 %0, {%1, %2};" : "=l"(r) : "f"(v), "f"(v)); return r;
}
__device__ __forceinline__ u64 fma2(u64 a, u64 b, u64 c) {
    u64 d; asm("fma.rn.f32x2 %0, %1, %2, %3;" : "=l"(d) : "l"(a), "l"(b), "l"(c)); return d;
}
__device__ __forceinline__ float2 unpack2(u64 v) {
    float2 f; asm("mov.b64 {%0, %1}, %2;" : "=f"(f.x), "=f"(f.y) : "l"(v)); return f;
}

// ---------------------------------------------------------------------------
// Kernel 1: node projection GEMM with packed f32x2 FMA.
//   half = blockIdx.y: 0 -> A (W1[:, 0:128], +b1), 1 -> B (W1[:, 128:256])
//   Block tile: 64 rows x 128 cols, K chunked by 32. 256 threads.
//   Per thread: 4 rows x 8 cols = 4 x 4 packed f32x2 accumulators.
// ---------------------------------------------------------------------------
__global__ __launch_bounds__(256) void node_proj_kernel(
    const float* __restrict__ x,    // [N_NODES, 128]
    const float* __restrict__ W1,   // [128, 256] row-major
    const float* __restrict__ b1)   // [128]
{
    const int half = blockIdx.y;
    const int row0 = blockIdx.x * 64;
    const int tid  = threadIdx.x;
    const int tx   = tid & 15;   // col group: cols 8*tx .. 8*tx+7
    const int ty   = tid >> 4;   // row group: rows 4*ty .. 4*ty+3
    const int woff = half * 128;

    // Fold the loss-sum zeroing into this kernel (runs before edge_kernel).
    if (blockIdx.x == 0 && half == 0 && tid == 0) g_loss_sum = 0.0;

    float* __restrict__ out = half ? g_B : g_A;

    __shared__ float xs[64 * 33];    // [64 rows][32 k], pitch 33
    __shared__ float ws[32 * 132];   // [32 k][128 j], pitch 132 (16B aligned rows)

    u64 acc2[4][4];
#pragma unroll
    for (int i = 0; i < 4; i++)
#pragma unroll
        for (int j = 0; j < 4; j++) acc2[i][j] = 0ULL;

    for (int kc = 0; kc < 128; kc += 32) {
#pragma unroll
        for (int idx = tid; idx < 64 * 32; idx += 256) {
            int r  = idx >> 5;
            int kk = idx & 31;
            int row = row0 + r;
            xs[r * 33 + kk] = (row < N_NODES) ? x[row * 128 + kc + kk] : 0.0f;
        }
#pragma unroll
        for (int idx = tid; idx < 32 * 128; idx += 256) {
            int kk = idx & 31;
            int j  = idx >> 5;
            ws[kk * 132 + j] = W1[j * 256 + woff + kc + kk];
        }
        __syncthreads();

#pragma unroll 4
        for (int kk = 0; kk < 32; kk++) {
            // Broadcast x values into packed duplicates.
            u64 xp[4];
#pragma unroll
            for (int i = 0; i < 4; i++)
                xp[i] = pack2_dup(xs[(4 * ty + i) * 33 + kk]);

            // W column pairs come packed for free from 128-bit shared loads.
            const ulonglong2* wr = (const ulonglong2*)(ws + kk * 132 + 8 * tx);
            ulonglong2 wv0 = wr[0];   // cols 8tx+0..3 as two f32x2
            ulonglong2 wv1 = wr[1];   // cols 8tx+4..7

#pragma unroll
            for (int i = 0; i < 4; i++) {
                acc2[i][0] = fma2(xp[i], wv0.x, acc2[i][0]);
                acc2[i][1] = fma2(xp[i], wv0.y, acc2[i][1]);
                acc2[i][2] = fma2(xp[i], wv1.x, acc2[i][2]);
                acc2[i][3] = fma2(xp[i], wv1.y, acc2[i][3]);
            }
        }
        __syncthreads();
    }

    // Unpack, fold bias (A half only), store with 128-bit writes.
    float bb[8];
    if (half == 0) {
#pragma unroll
        for (int j = 0; j < 8; j++) bb[j] = b1[8 * tx + j];
    } else {
#pragma unroll
        for (int j = 0; j < 8; j++) bb[j] = 0.0f;
    }

#pragma unroll
    for (int i = 0; i < 4; i++) {
        int row = row0 + 4 * ty + i;
        if (row < N_NODES) {
            float2 p0 = unpack2(acc2[i][0]);
            float2 p1 = unpack2(acc2[i][1]);
            float2 p2 = unpack2(acc2[i][2]);
            float2 p3 = unpack2(acc2[i][3]);
            float4* o = (float4*)(out + row * 128 + 8 * tx);
            o[0] = make_float4(p0.x + bb[0], p0.y + bb[1], p1.x + bb[2], p1.y + bb[3]);
            o[1] = make_float4(p2.x + bb[4], p2.y + bb[5], p3.x + bb[6], p3.y + bb[7]);
        }
    }
}

// ---------------------------------------------------------------------------
// Kernel 2: edge phase. One warp per edge (grid-stride), L2-resident gather.
//   z = sum_j relu(A[u][j] + B[v][j]) * w2[j] + b2
//   loss_e = max(z,0) - z*y + log1p(exp(-|z|))
// pairs is int32 (JAX x64 disabled downcasts the reference's int64).
// ---------------------------------------------------------------------------
__global__ __launch_bounds__(256) void edge_kernel(
    const int*   __restrict__ pairs,   // [2, E] int32
    const float* __restrict__ labels,  // [E]
    const float* __restrict__ W2,      // [128]
    const float* __restrict__ b2)      // [1]
{
    const int lane = threadIdx.x & 31;
    const int warp_global = (blockIdx.x * blockDim.x + threadIdx.x) >> 5;
    const int nwarps = (gridDim.x * blockDim.x) >> 5;

    const float4 w2 = ((const float4*)W2)[lane];
    const float bias2 = b2[0];

    float acc = 0.0f;

    for (int e = warp_global; e < E_TOTAL; e += nwarps) {
        int u = pairs[e];
        int v = pairs[E_TOTAL + e];
        const float4 a = ((const float4*)(g_A + (size_t)u * DIM))[lane];
        const float4 b = ((const float4*)(g_B + (size_t)v * DIM))[lane];

        float z;
        z = fmaxf(a.x + b.x, 0.0f) * w2.x;
        z = fmaf(fmaxf(a.y + b.y, 0.0f), w2.y, z);
        z = fmaf(fmaxf(a.z + b.z, 0.0f), w2.z, z);
        z = fmaf(fmaxf(a.w + b.w, 0.0f), w2.w, z);

#pragma unroll
        for (int off = 16; off; off >>= 1)
            z += __shfl_xor_sync(0xFFFFFFFFu, z, off);
        z += bias2;

        float y = labels[e];
        float loss = fmaxf(z, 0.0f) - z * y + log1pf(expf(-fabsf(z)));
        acc += loss;
    }

    __shared__ float wsum[8];
    if (lane == 0) wsum[threadIdx.x >> 5] = acc;
    __syncthreads();
    if (threadIdx.x == 0) {
        float s = 0.0f;
#pragma unroll
        for (int i = 0; i < 8; i++) s += wsum[i];
        atomicAdd(&g_loss_sum, (double)s);
    }
}

__global__ void finalize_kernel(float* __restrict__ out) {
    out[0] = (float)(g_loss_sum / (double)E_TOTAL);
}

// ---------------------------------------------------------------------------
// kernel_launch — input order: x, W1, b1, W2, b2, labels, pairs
// ---------------------------------------------------------------------------
extern "C" void kernel_launch(void* const* d_in, const int* in_sizes, int n_in,
                              void* d_out, int out_size) {
    const float* x      = (const float*)d_in[0];
    const float* W1     = (const float*)d_in[1];
    const float* b1     = (const float*)d_in[2];
    const float* W2     = (const float*)d_in[3];
    const float* b2     = (const float*)d_in[4];
    const float* labels = (const float*)d_in[5];
    const int*   pairs  = (const int*)d_in[6];
    float* out = (float*)d_out;

    dim3 ggrid((N_NODES + 63) / 64, 2);
    node_proj_kernel<<<ggrid, 256>>>(x, W1, b1);

    edge_kernel<<<1184, 256>>>(pairs, labels, W2, b2);

    finalize_kernel<<<1, 1>>>(out);
}

// round 5
// speedup vs baseline: 1.4097x; 1.3868x over previous
#include <cuda_runtime.h>
#include <cuda_bf16.h>

// Problem constants (match reference_code)
#define N_NODES 50000
#define DIM     128
#define E_TOTAL 600000
#define ROW_BLOCKS ((N_NODES + 127) / 128)   // 391

// Tables stored in bf16: halves the L2-resident edge-gather traffic.
__device__ __nv_bfloat16 g_A[N_NODES * DIM];
__device__ __nv_bfloat16 g_B[N_NODES * DIM];
// W1 pre-transposed per half: g_Wt[h][k*128 + j] = W1[j][h*128 + k]
__device__ float g_Wt[2][128 * 128];
__device__ double g_loss_sum;

typedef unsigned long long u64;

__device__ __forceinline__ u64 fma2(u64 a, u64 b, u64 c) {
    u64 d; asm("fma.rn.f32x2 %0, %1, %2, %3;" : "=l"(d) : "l"(a), "l"(b), "l"(c)); return d;
}
__device__ __forceinline__ u64 add2(u64 a, u64 b) {
    u64 d; asm("add.rn.f32x2 %0, %1, %2;" : "=l"(d) : "l"(a), "l"(b)); return d;
}
__device__ __forceinline__ u64 pack2(float lo, float hi) {
    u64 d; asm("mov.b64 %0, {%1, %2};" : "=l"(d) : "f"(lo), "f"(hi)); return d;
}
// Packed f32x2 -> bf16x2: unpack to two f32 then one cvt (cvt.rn.bf16x2.f32
// requires two .f32 source operands, not a packed .b64).
__device__ __forceinline__ unsigned cvt_bf16x2(u64 v) {
    float lo, hi;
    asm("mov.b64 {%0, %1}, %2;" : "=f"(lo), "=f"(hi) : "l"(v));
    unsigned r;
    asm("cvt.rn.bf16x2.f32 %0, %1, %2;" : "=r"(r) : "f"(hi), "f"(lo));
    return r;
}

// ---------------------------------------------------------------------------
// Kernel 0: one-shot W1 transpose (128KB; ~2-3us). Enables conflict-free,
// contiguous smem staging of W tiles in the GEMM.
// ---------------------------------------------------------------------------
__global__ void transpose_W_kernel(const float* __restrict__ W1) {
    int t = blockIdx.x * 256 + threadIdx.x;     // 0 .. 32767
    int j = t >> 8;          // output neuron 0..127
    int k = t & 255;         // input col 0..255
    g_Wt[k >> 7][(k & 127) * 128 + j] = W1[t];
}

// ---------------------------------------------------------------------------
// Kernel 1: node projection GEMM, 128x128 block tile, 8x8 per thread,
// packed f32x2 FMA. half=blockIdx.y: 0 -> A (+b1), 1 -> B.
// Thread (tx=tid&15, ty=tid>>4) owns rows 8ty..8ty+7, cols {4tx..4tx+3} and
// {64+4tx..64+4tx+3} (two contiguous float4 groups -> conflict-free LDS.128).
// x staged as duplicated f32x2 pairs -> broadcast LDS.64 per operand.
// ---------------------------------------------------------------------------
__global__ __launch_bounds__(256, 2) void node_proj_kernel(
    const float* __restrict__ x,    // [N_NODES, 128]
    const float* __restrict__ b1)   // [128]
{
    const int half = blockIdx.y;
    const int row0 = blockIdx.x * 128;
    const int tid  = threadIdx.x;
    const int tx   = tid & 15;
    const int ty   = tid >> 4;

    if (blockIdx.x == 0 && half == 0 && tid == 0) g_loss_sum = 0.0;

    __nv_bfloat16* __restrict__ out = half ? g_B : g_A;
    const float* __restrict__ Wt = g_Wt[half];

    __shared__ float xs[128 * 64];   // xs[r*64 + 2*kk] = dup pair of x[row0+r][kc+kk]
    __shared__ float ws[32 * 128];   // ws[kk*128 + j]

    u64 acc[8][4];
#pragma unroll
    for (int i = 0; i < 8; i++)
#pragma unroll
        for (int j = 0; j < 4; j++) acc[i][j] = 0ULL;

    for (int kc = 0; kc < 128; kc += 32) {
        // ws fill: contiguous 16KB copy from transposed W (coalesced, conflict-free)
#pragma unroll
        for (int i = tid; i < 1024; i += 256)
            ((float4*)ws)[i] = ((const float4*)(Wt + kc * 128))[i];
        // xs fill: coalesced global read, duplicated STS.64 store
#pragma unroll
        for (int i = tid; i < 4096; i += 256) {
            int r  = i >> 5;
            int kk = i & 31;
            int row = row0 + r;
            float v = (row < N_NODES) ? x[row * 128 + kc + kk] : 0.0f;
            ((float2*)xs)[r * 32 + kk] = make_float2(v, v);
        }
        __syncthreads();

#pragma unroll 8
        for (int kk = 0; kk < 32; kk++) {
            u64 xp[8];
#pragma unroll
            for (int i = 0; i < 8; i++)
                xp[i] = *(const u64*)(xs + (8 * ty + i) * 64 + 2 * kk);

            ulonglong2 wa = *(const ulonglong2*)(ws + kk * 128 + 4 * tx);       // cols 4tx..4tx+3
            ulonglong2 wb = *(const ulonglong2*)(ws + kk * 128 + 64 + 4 * tx);  // cols 64+4tx..

#pragma unroll
            for (int i = 0; i < 8; i++) {
                acc[i][0] = fma2(xp[i], wa.x, acc[i][0]);
                acc[i][1] = fma2(xp[i], wa.y, acc[i][1]);
                acc[i][2] = fma2(xp[i], wb.x, acc[i][2]);
                acc[i][3] = fma2(xp[i], wb.y, acc[i][3]);
            }
        }
        __syncthreads();
    }

    // Bias (A half only) packed as f32x2; zeros otherwise.
    u64 bb[4] = {0ULL, 0ULL, 0ULL, 0ULL};
    if (half == 0) {
        const float2* b2p = (const float2*)b1;
        float2 p0 = b2p[2 * tx];
        float2 p1 = b2p[2 * tx + 1];
        float2 p2 = b2p[32 + 2 * tx];
        float2 p3 = b2p[32 + 2 * tx + 1];
        bb[0] = pack2(p0.x, p0.y);
        bb[1] = pack2(p1.x, p1.y);
        bb[2] = pack2(p2.x, p2.y);
        bb[3] = pack2(p3.x, p3.y);
    }

#pragma unroll
    for (int i = 0; i < 8; i++) {
        int row = row0 + 8 * ty + i;
        if (row < N_NODES) {
            unsigned c0 = cvt_bf16x2(add2(acc[i][0], bb[0]));
            unsigned c1 = cvt_bf16x2(add2(acc[i][1], bb[1]));
            unsigned c2 = cvt_bf16x2(add2(acc[i][2], bb[2]));
            unsigned c3 = cvt_bf16x2(add2(acc[i][3], bb[3]));
            __nv_bfloat16* rp = out + (size_t)row * 128;
            *(uint2*)(rp + 4 * tx)      = make_uint2(c0, c1);
            *(uint2*)(rp + 64 + 4 * tx) = make_uint2(c2, c3);
        }
    }
}

// ---------------------------------------------------------------------------
// Kernel 2: edge phase. One warp per edge (grid-stride); bf16 tables are
// L2-resident (25.6MB total) -> gather traffic 307MB, L2-bound.
// pairs is int32 (JAX x64 disabled downcasts the reference's int64).
// ---------------------------------------------------------------------------
__global__ __launch_bounds__(256) void edge_kernel(
    const int*   __restrict__ pairs,   // [2, E] int32
    const float* __restrict__ labels,  // [E]
    const float* __restrict__ W2,      // [128]
    const float* __restrict__ b2)      // [1]
{
    const int lane = threadIdx.x & 31;
    const int warp_global = (blockIdx.x * blockDim.x + threadIdx.x) >> 5;
    const int nwarps = (gridDim.x * blockDim.x) >> 5;

    const float4 w2 = ((const float4*)W2)[lane];  // cols 4*lane..4*lane+3
    const float bias2 = b2[0];

    float acc = 0.0f;

    for (int e = warp_global; e < E_TOTAL; e += nwarps) {
        int u = pairs[e];
        int v = pairs[E_TOTAL + e];
        uint2 av = *(const uint2*)(g_A + (size_t)u * DIM + 4 * lane);
        uint2 bv = *(const uint2*)(g_B + (size_t)v * DIM + 4 * lane);

        float2 a0 = __bfloat1622float2(*(const __nv_bfloat162*)&av.x);
        float2 a1 = __bfloat1622float2(*(const __nv_bfloat162*)&av.y);
        float2 b0 = __bfloat1622float2(*(const __nv_bfloat162*)&bv.x);
        float2 b1 = __bfloat1622float2(*(const __nv_bfloat162*)&bv.y);

        float z;
        z = fmaxf(a0.x + b0.x, 0.0f) * w2.x;
        z = fmaf(fmaxf(a0.y + b0.y, 0.0f), w2.y, z);
        z = fmaf(fmaxf(a1.x + b1.x, 0.0f), w2.z, z);
        z = fmaf(fmaxf(a1.y + b1.y, 0.0f), w2.w, z);

#pragma unroll
        for (int off = 16; off; off >>= 1)
            z += __shfl_xor_sync(0xFFFFFFFFu, z, off);
        z += bias2;

        float y = labels[e];
        float loss = fmaxf(z, 0.0f) - z * y + log1pf(expf(-fabsf(z)));
        acc += loss;
    }

    __shared__ float wsum[8];
    if (lane == 0) wsum[threadIdx.x >> 5] = acc;
    __syncthreads();
    if (threadIdx.x == 0) {
        float s = 0.0f;
#pragma unroll
        for (int i = 0; i < 8; i++) s += wsum[i];
        atomicAdd(&g_loss_sum, (double)s);
    }
}

__global__ void finalize_kernel(float* __restrict__ out) {
    out[0] = (float)(g_loss_sum / (double)E_TOTAL);
}

// ---------------------------------------------------------------------------
// kernel_launch — input order: x, W1, b1, W2, b2, labels, pairs
// ---------------------------------------------------------------------------
extern "C" void kernel_launch(void* const* d_in, const int* in_sizes, int n_in,
                              void* d_out, int out_size) {
    const float* x      = (const float*)d_in[0];
    const float* W1     = (const float*)d_in[1];
    const float* b1     = (const float*)d_in[2];
    const float* W2     = (const float*)d_in[3];
    const float* b2     = (const float*)d_in[4];
    const float* labels = (const float*)d_in[5];
    const int*   pairs  = (const int*)d_in[6];
    float* out = (float*)d_out;

    transpose_W_kernel<<<128, 256>>>(W1);

    dim3 ggrid(ROW_BLOCKS, 2);
    node_proj_kernel<<<ggrid, 256>>>(x, b1);

    edge_kernel<<<1184, 256>>>(pairs, labels, W2, b2);

    finalize_kernel<<<1, 1>>>(out);
}

// round 6
// speedup vs baseline: 2.3153x; 1.6424x over previous
#include <cuda_runtime.h>
#include <cuda_bf16.h>

// Problem constants (match reference_code)
#define N_NODES 50000
#define DIM     128
#define E_TOTAL 600000
#define ROW_BLOCKS ((N_NODES + 127) / 128)   // 391
#define M_PAD (ROW_BLOCKS * 128)             // 50048

// bf16 copies of inputs for tensor-core GEMM. g_xb padded; pad rows are never
// written (stay zero from module load) and their outputs are never stored.
__device__ __nv_bfloat16 g_xb[(size_t)M_PAD * DIM];
__device__ __nv_bfloat16 g_Wb[2][DIM * DIM];   // [half][j*128 + k] = W1[j][h*128+k]
// Projection tables (bf16: halves L2 gather traffic in the edge phase).
__device__ __nv_bfloat16 g_A[(size_t)N_NODES * DIM];
__device__ __nv_bfloat16 g_B[(size_t)N_NODES * DIM];
__device__ double g_loss_sum;

// cvt.rn.bf16x2.f32 d, a, b  -> d = {hi=a, lo=b}
__device__ __forceinline__ unsigned cvt2(float hi, float lo) {
    unsigned r; asm("cvt.rn.bf16x2.f32 %0, %1, %2;" : "=r"(r) : "f"(hi), "f"(lo)); return r;
}

__device__ __forceinline__ void ldsm_x4(unsigned* r, unsigned addr) {
    asm volatile("ldmatrix.sync.aligned.m8n8.x4.shared.b16 {%0,%1,%2,%3}, [%4];"
                 : "=r"(r[0]), "=r"(r[1]), "=r"(r[2]), "=r"(r[3]) : "r"(addr));
}

__device__ __forceinline__ void mma_bf16(float* c, const unsigned* a, unsigned b0, unsigned b1) {
    asm volatile("mma.sync.aligned.m16n8k16.row.col.f32.bf16.bf16.f32 "
                 "{%0,%1,%2,%3}, {%4,%5,%6,%7}, {%8,%9}, {%0,%1,%2,%3};"
                 : "+f"(c[0]), "+f"(c[1]), "+f"(c[2]), "+f"(c[3])
                 : "r"(a[0]), "r"(a[1]), "r"(a[2]), "r"(a[3]), "r"(b0), "r"(b1));
}

// ---------------------------------------------------------------------------
// Kernel 0: fp32 -> bf16 conversion of x and W1 (one pass, ~39MB DRAM).
// ---------------------------------------------------------------------------
#define X_VEC (N_NODES * DIM / 4)     // 1,600,000 float4
#define W_VEC (DIM * 256 / 4)         // 8,192 float4
__global__ void convert_kernel(const float4* __restrict__ x, const float4* __restrict__ W1) {
    int i = blockIdx.x * 256 + threadIdx.x;
    if (i == 0) g_loss_sum = 0.0;
    if (i < X_VEC) {
        float4 v = x[i];
        ((uint2*)g_xb)[i] = make_uint2(cvt2(v.y, v.x), cvt2(v.w, v.z));
    } else if (i < X_VEC + W_VEC) {
        int t = i - X_VEC;            // float4 index into W1 [128][256]
        float4 v = W1[t];
        int j = t >> 6;               // row (output neuron)
        int c = (t & 63) * 4;         // col 0..252
        int h = c >> 7, k = c & 127;
        *(uint2*)(g_Wb[h] + j * DIM + k) = make_uint2(cvt2(v.y, v.x), cvt2(v.w, v.z));
    }
}

// ---------------------------------------------------------------------------
// Kernel 1: node projection GEMM on tensor cores (mma.sync m16n8k16 bf16).
// Block: 128 rows x 128 cols (half = blockIdx.y; 0 -> A (+b1), 1 -> B).
// 8 warps: warp_m = w&3 (32 rows), warp_n = w>>2 (64 cols).
// K chunked by 64; smem tiles pitch 72 bf16 (9 x 16B) -> conflict-free ldmatrix.
// ---------------------------------------------------------------------------
__global__ __launch_bounds__(256, 2) void gemm_kernel(const float* __restrict__ b1) {
    const int half = blockIdx.y;
    const int row0 = blockIdx.x * 128;
    const int tid  = threadIdx.x;
    const int lane = tid & 31;
    const int w    = tid >> 5;
    const int warp_m = w & 3;
    const int warp_n = w >> 2;

    __shared__ __nv_bfloat16 As[128 * 72];
    __shared__ __nv_bfloat16 Bs[128 * 72];

    const __nv_bfloat16* __restrict__ Wb = g_Wb[half];
    __nv_bfloat16* __restrict__ out = half ? g_B : g_A;

    float acc[2][8][4];
#pragma unroll
    for (int mt = 0; mt < 2; mt++)
#pragma unroll
        for (int nt = 0; nt < 8; nt++)
#pragma unroll
            for (int q = 0; q < 4; q++) acc[mt][nt][q] = 0.0f;

    // ldmatrix lane base addresses (byte offsets in shared space).
    // A (x4): lanes 0-15 rows m0..m0+15 k-lo(16B), lanes 16-31 same rows k-hi.
    unsigned a_base = (unsigned)__cvta_generic_to_shared(As)
        + (unsigned)(((32 * warp_m + (lane & 15)) * 72 + (lane >> 4) * 8) * 2);
    // B (x4): covers 2 n-tiles (16 n rows): groups of 8 lanes ->
    //   (n rows 0-7, k-lo), (rows 0-7, k-hi), (rows 8-15, k-lo), (rows 8-15, k-hi)
    unsigned b_base = (unsigned)__cvta_generic_to_shared(Bs)
        + (unsigned)(((64 * warp_n + (lane & 7) + ((lane >> 4) << 3)) * 72
                      + ((lane >> 3) & 1) * 8) * 2);

    for (int kc = 0; kc < 128; kc += 64) {
        // Stage tiles: 1024 uint4 each, coalesced, conflict-free stores.
#pragma unroll
        for (int i = tid; i < 1024; i += 256) {
            int r = i >> 3, c = i & 7;
            *(uint4*)(As + r * 72 + c * 8) =
                *(const uint4*)(g_xb + (size_t)(row0 + r) * DIM + kc + c * 8);
            *(uint4*)(Bs + r * 72 + c * 8) =
                *(const uint4*)(Wb + r * DIM + kc + c * 8);
        }
        __syncthreads();

#pragma unroll
        for (int ks = 0; ks < 4; ks++) {
            unsigned a0[4], a1[4];
            ldsm_x4(a0, a_base + ks * 32);                  // m tile 0
            ldsm_x4(a1, a_base + 16 * 144 + ks * 32);       // m tile 1 (+16 rows)
#pragma unroll
            for (int nt2 = 0; nt2 < 4; nt2++) {
                unsigned b[4];
                ldsm_x4(b, b_base + nt2 * 16 * 144 + ks * 32);
                mma_bf16(acc[0][2 * nt2],     a0, b[0], b[1]);
                mma_bf16(acc[1][2 * nt2],     a1, b[0], b[1]);
                mma_bf16(acc[0][2 * nt2 + 1], a0, b[2], b[3]);
                mma_bf16(acc[1][2 * nt2 + 1], a1, b[2], b[3]);
            }
        }
        __syncthreads();
    }

    // Epilogue: bias (A half only), pack to bf16x2, store.
    const int g = lane >> 2, t = lane & 3;
    const int col_base = 64 * warp_n;

    float2 bias[8];
#pragma unroll
    for (int nt = 0; nt < 8; nt++) bias[nt] = make_float2(0.0f, 0.0f);
    if (half == 0) {
#pragma unroll
        for (int nt = 0; nt < 8; nt++)
            bias[nt] = *(const float2*)(b1 + col_base + 8 * nt + 2 * t);
    }

#pragma unroll
    for (int mt = 0; mt < 2; mt++) {
        int row_lo = row0 + 32 * warp_m + 16 * mt + g;
        int row_hi = row_lo + 8;
#pragma unroll
        for (int nt = 0; nt < 8; nt++) {
            const float* c = acc[mt][nt];
            int col = col_base + 8 * nt + 2 * t;
            if (row_lo < N_NODES)
                *(unsigned*)(out + (size_t)row_lo * DIM + col) =
                    cvt2(c[1] + bias[nt].y, c[0] + bias[nt].x);
            if (row_hi < N_NODES)
                *(unsigned*)(out + (size_t)row_hi * DIM + col) =
                    cvt2(c[3] + bias[nt].y, c[2] + bias[nt].x);
        }
    }
}

// ---------------------------------------------------------------------------
// Kernel 2: edge phase. One warp per edge (grid-stride); bf16 tables are
// L2-resident (25.6MB) -> 307MB gather, L2-bound.
// pairs is int32 (JAX x64 disabled downcasts the reference's int64).
// ---------------------------------------------------------------------------
__global__ __launch_bounds__(256) void edge_kernel(
    const int*   __restrict__ pairs,   // [2, E] int32
    const float* __restrict__ labels,  // [E]
    const float* __restrict__ W2,      // [128]
    const float* __restrict__ b2)      // [1]
{
    const int lane = threadIdx.x & 31;
    const int warp_global = (blockIdx.x * blockDim.x + threadIdx.x) >> 5;
    const int nwarps = (gridDim.x * blockDim.x) >> 5;

    const float4 w2 = ((const float4*)W2)[lane];  // cols 4*lane..4*lane+3
    const float bias2 = b2[0];

    float acc = 0.0f;

    for (int e = warp_global; e < E_TOTAL; e += nwarps) {
        int u = pairs[e];
        int v = pairs[E_TOTAL + e];
        uint2 av = *(const uint2*)(g_A + (size_t)u * DIM + 4 * lane);
        uint2 bv = *(const uint2*)(g_B + (size_t)v * DIM + 4 * lane);

        float2 a0 = __bfloat1622float2(*(const __nv_bfloat162*)&av.x);
        float2 a1 = __bfloat1622float2(*(const __nv_bfloat162*)&av.y);
        float2 b0 = __bfloat1622float2(*(const __nv_bfloat162*)&bv.x);
        float2 b1 = __bfloat1622float2(*(const __nv_bfloat162*)&bv.y);

        float z;
        z = fmaxf(a0.x + b0.x, 0.0f) * w2.x;
        z = fmaf(fmaxf(a0.y + b0.y, 0.0f), w2.y, z);
        z = fmaf(fmaxf(a1.x + b1.x, 0.0f), w2.z, z);
        z = fmaf(fmaxf(a1.y + b1.y, 0.0f), w2.w, z);

#pragma unroll
        for (int off = 16; off; off >>= 1)
            z += __shfl_xor_sync(0xFFFFFFFFu, z, off);
        z += bias2;

        float y = labels[e];
        float loss = fmaxf(z, 0.0f) - z * y + log1pf(expf(-fabsf(z)));
        acc += loss;
    }

    __shared__ float wsum[8];
    if (lane == 0) wsum[threadIdx.x >> 5] = acc;
    __syncthreads();
    if (threadIdx.x == 0) {
        float s = 0.0f;
#pragma unroll
        for (int i = 0; i < 8; i++) s += wsum[i];
        atomicAdd(&g_loss_sum, (double)s);
    }
}

__global__ void finalize_kernel(float* __restrict__ out) {
    out[0] = (float)(g_loss_sum / (double)E_TOTAL);
}

// ---------------------------------------------------------------------------
// kernel_launch — input order: x, W1, b1, W2, b2, labels, pairs
// ---------------------------------------------------------------------------
extern "C" void kernel_launch(void* const* d_in, const int* in_sizes, int n_in,
                              void* d_out, int out_size) {
    const float* x      = (const float*)d_in[0];
    const float* W1     = (const float*)d_in[1];
    const float* b1     = (const float*)d_in[2];
    const float* W2     = (const float*)d_in[3];
    const float* b2     = (const float*)d_in[4];
    const float* labels = (const float*)d_in[5];
    const int*   pairs  = (const int*)d_in[6];
    float* out = (float*)d_out;

    convert_kernel<<<(X_VEC + W_VEC + 255) / 256, 256>>>((const float4*)x, (const float4*)W1);

    dim3 ggrid(ROW_BLOCKS, 2);
    gemm_kernel<<<ggrid, 256>>>(b1);

    edge_kernel<<<1184, 256>>>(pairs, labels, W2, b2);

    finalize_kernel<<<1, 1>>>(out);
}